// round 12
// baseline (speedup 1.0000x reference)
#include <cuda_runtime.h>
#include <cuda_bf16.h>

// x[B=16, H=256, W=256, C=3, L=8] fp32 -> out[16,3,8,8]
// CHN = C*L = 24 floats = 6 float4 per (b,h,w) position.
#define HW    256
#define CHN   24
#define CHUNK 32          // output cols per CTA
#define RT    64          // output rows per CTA
#define BLK   192
#define NCMAX 39          // cols incl. 7 halo
#define P2W   204         // p2 plane width (34 cols * 6)
#define ST2   210         // p2 row stride (== 2 mod 8 -> conflict-free)
#define ST4   234         // p4 row stride (== 2 mod 8)
#define RING  12          // 12*ST == 0 mod 8 -> wrap keeps bank phase
#define SMEM_F4  (RING * (ST2 + ST4))   // 5328 float4
#define SMEMBYTES (SMEM_F4 * 16)        // 85248 B -> 2 CTAs/SM

__device__ __forceinline__ float4 fmax4(float4 a, float4 b) {
    return make_float4(fmaxf(a.x, b.x), fmaxf(a.y, b.y),
                       fmaxf(a.z, b.z), fmaxf(a.w, b.w));
}
__device__ __forceinline__ void fadd4(float4& a, float4 b) {
    a.x += b.x; a.y += b.y; a.z += b.z; a.w += b.w;
}

// Ring update for one item of input row rr: p2[rr-3] (delayed 2) and p4[rr-3]
// written while processing rr; bottom edge flushes p2[253], p2[254].
// Slot computed internally per call: independent work, no loop-carried chain.
__device__ __forceinline__ void ring_update(
    int rr, int r0, int rtEnd, int f, bool own, float4 xv,
    float4& xp, float4& m1, float4& m2,
    float4* __restrict__ P2, float4* __restrict__ P4, float4& acc0)
{
    if (own && rr < rtEnd) fadd4(acc0, xv);          // scale 1
    if (rr > r0) {
        float4 p2v = fmax4(xv, xp);                  // p2[rr-1]
        if (rr >= r0 + 3) {
            const int ws = (rr - 3) % RING;
            if (f < P2W) P2[ws * ST2 + f] = m2;      // p2[rr-3]
            P4[ws * ST4 + f] = fmax4(m2, p2v);       // p4[rr-3]
        }
        if (rr == HW - 1 && f < P2W) {               // bottom-edge p2 flush
            P2[((HW - 3) % RING) * ST2 + f] = m1;    // p2[253]
            P2[((HW - 2) % RING) * ST2 + f] = p2v;   // p2[254]
        }
        m2 = m1; m1 = p2v;
    }
    xp = xv;
}

// CTA = (batch, 64-row strip, 32-col chunk + 7 halo cols).
// PIPELINED iteration: ring updates (slots i+4..i+7), LDG prefetch, and
// phase B for DELAYED output rows i-4..i-1 (reads slots i-4..i, all written
// >= 1 batch ago) are mutually independent; ONE trailing __syncthreads
// orders next batch's slot reuse (live span i-4..i+7 = exactly 12 slots).
__global__ __launch_bounds__(BLK, 2)
void sgb_main(const float* __restrict__ x, float* __restrict__ out) {
    extern __shared__ float4 sm[];
    float4* P2 = sm;                  // RING x ST2
    float4* P4 = sm + RING * ST2;     // RING x ST4

    const int t  = threadIdx.x;
    const int b  = blockIdx.z;
    const int r0 = blockIdx.y * RT;
    const int c0 = blockIdx.x * CHUNK;
    const int ncols = min(NCMAX, HW - c0);
    const int NF = ncols * 6;
    const int rtEnd = r0 + RT;
    const int rowmax = min(HW - 1, r0 + RT + 6);

    const bool has2 = (t + BLK < NF);
    float4 xp0 = {0,0,0,0}, m1_0 = {0,0,0,0}, m2_0 = {0,0,0,0};
    float4 xp1 = {0,0,0,0}, m1_1 = {0,0,0,0}, m2_1 = {0,0,0,0};
    float4 xbuf0[4], xbuf1[4];

    // phase-B mapping: t = ((g*6 + ch4)*4 + ri)
    const int ri  = t & 3;
    const int gch = t >> 2;
    const int ch4 = gch % 6;
    const int g   = gch / 6;
    const int baseitem = g * 24 + ch4;
    const int collim = HW - (c0 + g * 4);

    float4 acc[8];
#pragma unroll
    for (int s = 0; s < 8; ++s) acc[s] = make_float4(0.f, 0.f, 0.f, 0.f);

    const float4* X = (const float4*)x;

    // ---- prologue: rows r0..r0+6 direct; prefetch r0+7..r0+10 ----
    for (int rr = r0; rr <= r0 + 6; ++rr) {
        const float4* grow = X + ((size_t)(b * HW + rr) * HW + c0) * 6;
        ring_update(rr, r0, rtEnd, t, true, grow[t], xp0, m1_0, m2_0, P2, P4, acc[0]);
        if (has2)
            ring_update(rr, r0, rtEnd, t + BLK, false, grow[t + BLK], xp1, m1_1, m2_1, P2, P4, acc[0]);
    }
#pragma unroll
    for (int q = 0; q < 4; ++q) {
        const int rr = r0 + 7 + q;
        if (rr <= rowmax) {
            const float4* grow = X + ((size_t)(b * HW + rr) * HW + c0) * 6;
            xbuf0[q] = grow[t];
            if (has2) xbuf1[q] = grow[t + BLK];
        }
    }
    // ---- iteration 0 (no phase B yet): rings rows r0+7..r0+10, prefetch ----
#pragma unroll
    for (int q = 0; q < 4; ++q) {
        const int rr = r0 + 7 + q;
        if (rr <= rowmax) {
            ring_update(rr, r0, rtEnd, t, true, xbuf0[q], xp0, m1_0, m2_0, P2, P4, acc[0]);
            if (has2)
                ring_update(rr, r0, rtEnd, t + BLK, false, xbuf1[q], xp1, m1_1, m2_1, P2, P4, acc[0]);
        }
    }
#pragma unroll
    for (int q = 0; q < 4; ++q) {
        const int rr = r0 + 11 + q;
        if (rr <= rowmax) {
            const float4* grow = X + ((size_t)(b * HW + rr) * HW + c0) * 6;
            xbuf0[q] = grow[t];
            if (has2) xbuf1[q] = grow[t + BLK];
        }
    }
    __syncthreads();

    // ---- main loop: k = 1..16 ; i = r0 + 4k ----
    for (int i = r0 + 4; i <= r0 + RT; i += 4) {
        // ring updates rows i+7..i+10 -> slots i+4..i+7 (guarded by rowmax)
#pragma unroll
        for (int q = 0; q < 4; ++q) {
            const int rr = i + 7 + q;
            if (rr <= rowmax) {
                ring_update(rr, r0, rtEnd, t, true, xbuf0[q], xp0, m1_0, m2_0, P2, P4, acc[0]);
                if (has2)
                    ring_update(rr, r0, rtEnd, t + BLK, false, xbuf1[q], xp1, m1_1, m2_1, P2, P4, acc[0]);
            }
        }
        // prefetch rows i+11..i+14
#pragma unroll
        for (int q = 0; q < 4; ++q) {
            const int rr = i + 11 + q;
            if (rr <= rowmax) {
                const float4* grow = X + ((size_t)(b * HW + rr) * HW + c0) * 6;
                xbuf0[q] = grow[t];
                if (has2) xbuf1[q] = grow[t + BLK];
            }
        }

        // ---- phase B (DELAYED): output row o = i - 4 + ri ----
        const int o = i - 4 + ri;
        const int rlim = HW - o;
        const float4* p2o  = P2 + ((o    ) % RING) * ST2 + baseitem;
        const float4* p2o1 = P2 + ((o + 1) % RING) * ST2 + baseitem;
        const float4* p4o  = P4 + ((o    ) % RING) * ST4 + baseitem;
        const float4* p4o1 = P4 + ((o + 1) % RING) * ST4 + baseitem;
        const float4* p4o2 = P4 + ((o + 2) % RING) * ST4 + baseitem;
        const float4* p4o3 = P4 + ((o + 3) % RING) * ST4 + baseitem;
        const float4* p4o4 = P4 + ((o + 4) % RING) * ST4 + baseitem;

        // scales 2,3 from p2 (independent chains)
        {
            float4 a[6];
#pragma unroll
            for (int k = 0; k < 6; ++k) a[k] = p2o[6 * k];
            if (rlim >= 2) {
                float4 s = make_float4(0.f, 0.f, 0.f, 0.f);
#pragma unroll
                for (int j = 0; j < 4; ++j)
                    if (j + 2 <= collim) fadd4(s, fmax4(a[j], a[j + 1]));
                fadd4(acc[1], s);
            }
            if (rlim >= 3) {
                float4 bb[6];
#pragma unroll
                for (int k = 0; k < 6; ++k) bb[k] = fmax4(a[k], p2o1[6 * k]);
                float4 s = make_float4(0.f, 0.f, 0.f, 0.f);
#pragma unroll
                for (int j = 0; j < 4; ++j)
                    if (j + 3 <= collim)
                        fadd4(s, fmax4(fmax4(bb[j], bb[j + 1]), bb[j + 2]));
                fadd4(acc[2], s);
            }
        }
        // scales 4..8 from p4: a4 shared, fresh bb per scale (independent)
        {
            float4 a4[11];
#pragma unroll
            for (int k = 0; k < 11; ++k) a4[k] = p4o[6 * k];
            if (rlim >= 4) {
                float4 m2[6];
#pragma unroll
                for (int k = 0; k < 6; ++k) m2[k] = fmax4(a4[k], a4[k + 1]);
                float4 s = make_float4(0.f, 0.f, 0.f, 0.f);
#pragma unroll
                for (int j = 0; j < 4; ++j)
                    if (j + 4 <= collim) fadd4(s, fmax4(m2[j], m2[j + 2]));
                fadd4(acc[3], s);
            }
            if (rlim >= 5) {
                float4 bb[8];
#pragma unroll
                for (int k = 0; k < 8; ++k) bb[k] = fmax4(a4[k], p4o1[6 * k]);
                float4 m2[6];
#pragma unroll
                for (int k = 0; k < 6; ++k) m2[k] = fmax4(bb[k], bb[k + 1]);
                float4 s = make_float4(0.f, 0.f, 0.f, 0.f);
#pragma unroll
                for (int j = 0; j < 4; ++j)
                    if (j + 5 <= collim)
                        fadd4(s, fmax4(fmax4(m2[j], m2[j + 2]), bb[j + 4]));
                fadd4(acc[4], s);
            }
            if (rlim >= 6) {
                float4 bb[9];
#pragma unroll
                for (int k = 0; k < 9; ++k) bb[k] = fmax4(a4[k], p4o2[6 * k]);
                float4 m2[8];
#pragma unroll
                for (int k = 0; k < 8; ++k) m2[k] = fmax4(bb[k], bb[k + 1]);
                float4 s = make_float4(0.f, 0.f, 0.f, 0.f);
#pragma unroll
                for (int j = 0; j < 4; ++j)
                    if (j + 6 <= collim)
                        fadd4(s, fmax4(fmax4(m2[j], m2[j + 2]), m2[j + 4]));
                fadd4(acc[5], s);
            }
            if (rlim >= 7) {
                float4 bb[10];
#pragma unroll
                for (int k = 0; k < 10; ++k) bb[k] = fmax4(a4[k], p4o3[6 * k]);
                float4 m2[9];
#pragma unroll
                for (int k = 0; k < 9; ++k) m2[k] = fmax4(bb[k], bb[k + 1]);
                float4 m4[7];
#pragma unroll
                for (int j = 0; j < 7; ++j) m4[j] = fmax4(m2[j], m2[j + 2]);
                float4 s = make_float4(0.f, 0.f, 0.f, 0.f);
#pragma unroll
                for (int j = 0; j < 4; ++j)
                    if (j + 7 <= collim) fadd4(s, fmax4(m4[j], m4[j + 3]));
                fadd4(acc[6], s);
            }
            if (rlim >= 8) {
                float4 bb[11];
#pragma unroll
                for (int k = 0; k < 11; ++k) bb[k] = fmax4(a4[k], p4o4[6 * k]);
                float4 m2[10];
#pragma unroll
                for (int k = 0; k < 10; ++k) m2[k] = fmax4(bb[k], bb[k + 1]);
                float4 m4[8];
#pragma unroll
                for (int j = 0; j < 8; ++j) m4[j] = fmax4(m2[j], m2[j + 2]);
                float4 s = make_float4(0.f, 0.f, 0.f, 0.f);
#pragma unroll
                for (int j = 0; j < 4; ++j)
                    if (j + 8 <= collim) fadd4(s, fmax4(m4[j], m4[j + 4]));
                fadd4(acc[7], s);
            }
        }
        __syncthreads();   // trailing: orders next batch's slot reuse
    }

    // ---- block reduction: 32 owners per (ch4, scale); stride-33 pad ----
    float4* red = sm;                 // 48*33 float4, reuses rings
    red[((t % 6) * 8 + 0) * 33 + (t / 6)] = acc[0];     // scale 1 (load mapping)
#pragma unroll
    for (int si = 1; si < 8; ++si)
        red[(ch4 * 8 + si) * 33 + (g * 4 + ri)] = acc[si];
    __syncthreads();
    if (t < 48) {
        const int c4 = t >> 3, si = t & 7;
        float4 s = make_float4(0.f, 0.f, 0.f, 0.f);
        const float4* row = red + (c4 * 8 + si) * 33;
#pragma unroll 8
        for (int w = 0; w < 32; ++w) fadd4(s, row[w]);
        float* op = out + (size_t)b * (CHN * 8) + si;
        atomicAdd(op + (c4 * 4 + 0) * 8, s.x);
        atomicAdd(op + (c4 * 4 + 1) * 8, s.y);
        atomicAdd(op + (c4 * 4 + 2) * 8, s.z);
        atomicAdd(op + (c4 * 4 + 3) * 8, s.w);
    }
}

__global__ void sgb_zero(float* __restrict__ out) {
    int i = blockIdx.x * blockDim.x + threadIdx.x;
    if (i < 16 * CHN * 8) out[i] = 0.f;
}

__global__ void sgb_finalize(float* __restrict__ out) {
    int i = blockIdx.x * blockDim.x + threadIdx.x;
    if (i < 16 * CHN * 8) out[i] = fmaxf(out[i], 0.f) + 1.f;
}

extern "C" void kernel_launch(void* const* d_in, const int* in_sizes, int n_in,
                              void* d_out, int out_size) {
    (void)in_sizes; (void)n_in; (void)out_size;
    const float* x = (const float*)d_in[0];   // x[16,256,256,3,8] fp32
    float* out = (float*)d_out;               // [16,3,8,8] fp32

    cudaFuncSetAttribute(sgb_main,
                         cudaFuncAttributeMaxDynamicSharedMemorySize,
                         SMEMBYTES);

    sgb_zero<<<12, 256>>>(out);
    dim3 grid(HW / CHUNK, HW / RT, 16);       // (8 chunks, 4 strips, 16 b) = 512 CTAs
    sgb_main<<<grid, BLK, SMEMBYTES>>>(x, out);
    sgb_finalize<<<12, 256>>>(out);
}

// round 13
// speedup vs baseline: 1.2793x; 1.2793x over previous
#include <cuda_runtime.h>
#include <cuda_bf16.h>

// x[B=16, H=256, W=256, C=3, L=8] fp32 -> out[16,3,8,8]
// CHN = C*L = 24 floats = 6 float4 per (b,h,w) position.
#define HW    256
#define CHN   24
#define CHUNK 32          // output cols per CTA
#define RT    64          // output rows per CTA
#define BLK   192
#define NCMAX 39          // cols incl. 7 halo
#define P2W   204         // p2 plane width (34 cols * 6)
#define ST2   210         // p2 row stride (== 2 mod 8 -> conflict-free)
#define ST4   234         // p4 row stride (== 2 mod 8)
#define RING  12          // 12*ST == 0 mod 8 -> wrap keeps bank phase
#define SMEM_F4  (RING * (ST2 + ST4))   // 5328 float4
#define SMEMBYTES (SMEM_F4 * 16)        // 85248 B -> 2 CTAs/SM

__device__ __forceinline__ float4 fmax4(float4 a, float4 b) {
    return make_float4(fmaxf(a.x, b.x), fmaxf(a.y, b.y),
                       fmaxf(a.z, b.z), fmaxf(a.w, b.w));
}
__device__ __forceinline__ void fadd4(float4& a, float4 b) {
    a.x += b.x; a.y += b.y; a.z += b.z; a.w += b.w;
}

// Ring update for one item of input row rr: p2[rr-3] (delayed 2) and p4[rr-3]
// written while processing rr; bottom edge flushes p2[253], p2[254].
// Slot computed internally per call: independent work, no loop-carried chain.
__device__ __forceinline__ void ring_update(
    int rr, int r0, int rtEnd, int f, bool own, float4 xv,
    float4& xp, float4& m1, float4& m2,
    float4* __restrict__ P2, float4* __restrict__ P4, float4& acc0)
{
    if (own && rr < rtEnd) fadd4(acc0, xv);          // scale 1
    if (rr > r0) {
        float4 p2v = fmax4(xv, xp);                  // p2[rr-1]
        if (rr >= r0 + 3) {
            const int ws = (rr - 3) % RING;
            if (f < P2W) P2[ws * ST2 + f] = m2;      // p2[rr-3]
            P4[ws * ST4 + f] = fmax4(m2, p2v);       // p4[rr-3]
        }
        if (rr == HW - 1 && f < P2W) {               // bottom-edge p2 flush
            P2[((HW - 3) % RING) * ST2 + f] = m1;    // p2[253]
            P2[((HW - 2) % RING) * ST2 + f] = p2v;   // p2[254]
        }
        m2 = m1; m1 = p2v;
    }
    xp = xv;
}

// CTA = (batch, 64-row strip, 32-col chunk + 7 halo cols). Per 4-row batch:
// ring-update rows i+7..i+10 from prefetched regs, issue LDGs for i+11..i+14,
// ONE sync, then phase B computes horizontal window maxes for output rows
// i..i+3 with INDEPENDENT per-scale chains (fresh bb[] per scale -> ILP).
// Warps finishing phase B early roll into the next iteration's independent
// ring/LDG work before the sync -> natural pipelining.
__global__ __launch_bounds__(BLK, 2)
void sgb_main(const float* __restrict__ x, float* __restrict__ out) {
    extern __shared__ float4 sm[];
    float4* P2 = sm;                  // RING x ST2
    float4* P4 = sm + RING * ST2;     // RING x ST4

    const int t  = threadIdx.x;
    const int b  = blockIdx.z;
    const int r0 = blockIdx.y * RT;
    const int c0 = blockIdx.x * CHUNK;
    const int ncols = min(NCMAX, HW - c0);
    const int NF = ncols * 6;
    const int rtEnd = r0 + RT;
    const int rowmax = min(HW - 1, r0 + RT + 6);

    const bool has2 = (t + BLK < NF);
    float4 xp0 = {0,0,0,0}, m1_0 = {0,0,0,0}, m2_0 = {0,0,0,0};
    float4 xp1 = {0,0,0,0}, m1_1 = {0,0,0,0}, m2_1 = {0,0,0,0};
    float4 xbuf0[4], xbuf1[4];

    // phase-B mapping: t = ((g*6 + ch4)*4 + ri)
    const int ri  = t & 3;
    const int gch = t >> 2;
    const int ch4 = gch % 6;
    const int g   = gch / 6;
    const int baseitem = g * 24 + ch4;
    const int collim = HW - (c0 + g * 4);

    float4 acc[8];
#pragma unroll
    for (int s = 0; s < 8; ++s) acc[s] = make_float4(0.f, 0.f, 0.f, 0.f);

    const float4* X = (const float4*)x;

    // ---- prologue: rows r0..r0+6 direct; prefetch r0+7..r0+10 ----
    for (int rr = r0; rr <= r0 + 6; ++rr) {
        const float4* grow = X + ((size_t)(b * HW + rr) * HW + c0) * 6;
        ring_update(rr, r0, rtEnd, t, true, grow[t], xp0, m1_0, m2_0, P2, P4, acc[0]);
        if (has2)
            ring_update(rr, r0, rtEnd, t + BLK, false, grow[t + BLK], xp1, m1_1, m2_1, P2, P4, acc[0]);
    }
#pragma unroll
    for (int q = 0; q < 4; ++q) {
        const int rr = r0 + 7 + q;
        if (rr <= rowmax) {
            const float4* grow = X + ((size_t)(b * HW + rr) * HW + c0) * 6;
            xbuf0[q] = grow[t];
            if (has2) xbuf1[q] = grow[t + BLK];
        }
    }

    for (int i = r0; i < r0 + RT; i += 4) {
        // ---- ring updates for rows i+7..i+10 (from prefetched regs) ----
#pragma unroll
        for (int q = 0; q < 4; ++q) {
            const int rr = i + 7 + q;
            if (rr <= rowmax) {
                ring_update(rr, r0, rtEnd, t, true, xbuf0[q], xp0, m1_0, m2_0, P2, P4, acc[0]);
                if (has2)
                    ring_update(rr, r0, rtEnd, t + BLK, false, xbuf1[q], xp1, m1_1, m2_1, P2, P4, acc[0]);
            }
        }
        // ---- prefetch rows i+11..i+14 (latency hidden by phase B) ----
#pragma unroll
        for (int q = 0; q < 4; ++q) {
            const int rr = i + 11 + q;
            if (rr <= rowmax) {
                const float4* grow = X + ((size_t)(b * HW + rr) * HW + c0) * 6;
                xbuf0[q] = grow[t];
                if (has2) xbuf1[q] = grow[t + BLK];
            }
        }
        __syncthreads();

        // ---- phase B: output row o = i + ri ----
        const int o = i + ri;
        const int rlim = HW - o;
        const float4* p2o  = P2 + ((o    ) % RING) * ST2 + baseitem;
        const float4* p2o1 = P2 + ((o + 1) % RING) * ST2 + baseitem;
        const float4* p4o  = P4 + ((o    ) % RING) * ST4 + baseitem;
        const float4* p4o1 = P4 + ((o + 1) % RING) * ST4 + baseitem;
        const float4* p4o2 = P4 + ((o + 2) % RING) * ST4 + baseitem;
        const float4* p4o3 = P4 + ((o + 3) % RING) * ST4 + baseitem;
        const float4* p4o4 = P4 + ((o + 4) % RING) * ST4 + baseitem;

        // scales 2,3 from p2 (independent chains)
        {
            float4 a[6];
#pragma unroll
            for (int k = 0; k < 6; ++k) a[k] = p2o[6 * k];
            if (rlim >= 2) {
                float4 s = make_float4(0.f, 0.f, 0.f, 0.f);
#pragma unroll
                for (int j = 0; j < 4; ++j)
                    if (j + 2 <= collim) fadd4(s, fmax4(a[j], a[j + 1]));
                fadd4(acc[1], s);
            }
            if (rlim >= 3) {
                float4 bb[6];
#pragma unroll
                for (int k = 0; k < 6; ++k) bb[k] = fmax4(a[k], p2o1[6 * k]);
                float4 s = make_float4(0.f, 0.f, 0.f, 0.f);
#pragma unroll
                for (int j = 0; j < 4; ++j)
                    if (j + 3 <= collim)
                        fadd4(s, fmax4(fmax4(bb[j], bb[j + 1]), bb[j + 2]));
                fadd4(acc[2], s);
            }
        }
        // scales 4..8 from p4: a4 shared, fresh bb per scale (independent)
        {
            float4 a4[11];
#pragma unroll
            for (int k = 0; k < 11; ++k) a4[k] = p4o[6 * k];
            if (rlim >= 4) {
                float4 m2[6];
#pragma unroll
                for (int k = 0; k < 6; ++k) m2[k] = fmax4(a4[k], a4[k + 1]);
                float4 s = make_float4(0.f, 0.f, 0.f, 0.f);
#pragma unroll
                for (int j = 0; j < 4; ++j)
                    if (j + 4 <= collim) fadd4(s, fmax4(m2[j], m2[j + 2]));
                fadd4(acc[3], s);
            }
            if (rlim >= 5) {
                float4 bb[8];
#pragma unroll
                for (int k = 0; k < 8; ++k) bb[k] = fmax4(a4[k], p4o1[6 * k]);
                float4 m2[6];
#pragma unroll
                for (int k = 0; k < 6; ++k) m2[k] = fmax4(bb[k], bb[k + 1]);
                float4 s = make_float4(0.f, 0.f, 0.f, 0.f);
#pragma unroll
                for (int j = 0; j < 4; ++j)
                    if (j + 5 <= collim)
                        fadd4(s, fmax4(fmax4(m2[j], m2[j + 2]), bb[j + 4]));
                fadd4(acc[4], s);
            }
            if (rlim >= 6) {
                float4 bb[9];
#pragma unroll
                for (int k = 0; k < 9; ++k) bb[k] = fmax4(a4[k], p4o2[6 * k]);
                float4 m2[8];
#pragma unroll
                for (int k = 0; k < 8; ++k) m2[k] = fmax4(bb[k], bb[k + 1]);
                float4 s = make_float4(0.f, 0.f, 0.f, 0.f);
#pragma unroll
                for (int j = 0; j < 4; ++j)
                    if (j + 6 <= collim)
                        fadd4(s, fmax4(fmax4(m2[j], m2[j + 2]), m2[j + 4]));
                fadd4(acc[5], s);
            }
            if (rlim >= 7) {
                float4 bb[10];
#pragma unroll
                for (int k = 0; k < 10; ++k) bb[k] = fmax4(a4[k], p4o3[6 * k]);
                float4 m2[9];
#pragma unroll
                for (int k = 0; k < 9; ++k) m2[k] = fmax4(bb[k], bb[k + 1]);
                float4 m4[7];
#pragma unroll
                for (int j = 0; j < 7; ++j) m4[j] = fmax4(m2[j], m2[j + 2]);
                float4 s = make_float4(0.f, 0.f, 0.f, 0.f);
#pragma unroll
                for (int j = 0; j < 4; ++j)
                    if (j + 7 <= collim) fadd4(s, fmax4(m4[j], m4[j + 3]));
                fadd4(acc[6], s);
            }
            if (rlim >= 8) {
                float4 bb[11];
#pragma unroll
                for (int k = 0; k < 11; ++k) bb[k] = fmax4(a4[k], p4o4[6 * k]);
                float4 m2[10];
#pragma unroll
                for (int k = 0; k < 10; ++k) m2[k] = fmax4(bb[k], bb[k + 1]);
                float4 m4[8];
#pragma unroll
                for (int j = 0; j < 8; ++j) m4[j] = fmax4(m2[j], m2[j + 2]);
                float4 s = make_float4(0.f, 0.f, 0.f, 0.f);
#pragma unroll
                for (int j = 0; j < 4; ++j)
                    if (j + 8 <= collim) fadd4(s, fmax4(m4[j], m4[j + 4]));
                fadd4(acc[7], s);
            }
        }
        // no trailing sync: next iteration's ring writes (slots i+8..i+11)
        // are disjoint mod 12 from this phase B's reads (slots i..i+7).
    }

    // ---- block reduction: 32 owners per (ch4, scale); stride-33 pad ----
    __syncthreads();
    float4* red = sm;                 // 48*33 float4, reuses rings
    red[((t % 6) * 8 + 0) * 33 + (t / 6)] = acc[0];     // scale 1 (load mapping)
#pragma unroll
    for (int si = 1; si < 8; ++si)
        red[(ch4 * 8 + si) * 33 + (g * 4 + ri)] = acc[si];
    __syncthreads();
    if (t < 48) {
        const int c4 = t >> 3, si = t & 7;
        float4 s = make_float4(0.f, 0.f, 0.f, 0.f);
        const float4* row = red + (c4 * 8 + si) * 33;
#pragma unroll 8
        for (int w = 0; w < 32; ++w) fadd4(s, row[w]);
        float* op = out + (size_t)b * (CHN * 8) + si;
        atomicAdd(op + (c4 * 4 + 0) * 8, s.x);
        atomicAdd(op + (c4 * 4 + 1) * 8, s.y);
        atomicAdd(op + (c4 * 4 + 2) * 8, s.z);
        atomicAdd(op + (c4 * 4 + 3) * 8, s.w);
    }
}

__global__ void sgb_finalize(float* __restrict__ out) {
    int i = blockIdx.x * blockDim.x + threadIdx.x;
    if (i < 16 * CHN * 8) out[i] = fmaxf(out[i], 0.f) + 1.f;
}

extern "C" void kernel_launch(void* const* d_in, const int* in_sizes, int n_in,
                              void* d_out, int out_size) {
    (void)in_sizes; (void)n_in;
    const float* x = (const float*)d_in[0];   // x[16,256,256,3,8] fp32
    float* out = (float*)d_out;               // [16,3,8,8] fp32

    cudaFuncSetAttribute(sgb_main,
                         cudaFuncAttributeMaxDynamicSharedMemorySize,
                         SMEMBYTES);

    // zero the accumulator via async memset (graph-capturable, replaces the
    // sgb_zero kernel launch); fp32 0.0f == all-zero bytes.
    cudaMemsetAsync(d_out, 0, (size_t)out_size * sizeof(float), 0);
    dim3 grid(HW / CHUNK, HW / RT, 16);       // (8 chunks, 4 strips, 16 b) = 512 CTAs
    sgb_main<<<grid, BLK, SMEMBYTES>>>(x, out);
    sgb_finalize<<<12, 256>>>(out);
}